// round 4
// baseline (speedup 1.0000x reference)
#include <cuda_runtime.h>
#include <cuda_bf16.h>
#include <cstdint>

// ---------------------------------------------------------------------------
// GCN: out = FC( relu(GCNConv2( relu(GCNConv1(x)) )) )
//   GCNConv(x): h = x@W;  out[d] = sum_{(s,d) in E} h[s]*dinv[s]*dinv[d]
//                                + h[d]*dinv[d]^2  (self loop) + b
// Edge dtype (int32 vs int64) detected on-device; edges converted to int32
// scratch once per call. Scratch = __device__ globals selected inside kernels.
// ---------------------------------------------------------------------------

#define N_MAX 100000
#define E_MAX 1600000
#define F_IN  128
#define F_HID 64
#define F_OUT 32

__device__ int   g_is64;
__device__ int   g_src32[E_MAX];
__device__ int   g_dst32[E_MAX];
__device__ int   g_deg[N_MAX];
__device__ float g_dinv[N_MAX];
__device__ int   g_rowstart[N_MAX + 1];
__device__ int   g_cursor[N_MAX];
__device__ int   g_colsrc[E_MAX];
__device__ int   g_blocksums[128];
__device__ float g_bufA[N_MAX * F_HID];
__device__ float g_bufB[N_MAX * F_HID];

__device__ __forceinline__ const float* pick_src(int sel, const float* ext) {
    if (sel == 1) return g_bufA;
    if (sel == 2) return g_bufB;
    return ext;
}
__device__ __forceinline__ float* pick_dst(int sel, float* ext) {
    if (sel == 1) return g_bufA;
    if (sel == 2) return g_bufB;
    return ext;
}

// ------------------------ edge dtype detect + convert ----------------------
// If edge_index is int64 (little-endian, values < 2^31), the high 32-bit word
// of every element is 0. If int32, "high words" are random edge IDs.

__global__ void detect_kernel(const int* __restrict__ ew, int E) {
    if (blockIdx.x == 0 && threadIdx.x == 0) {
        int is64 = 1;
        for (int i = 0; i < 32; ++i)
            if (ew[2 * i + 1] != 0) { is64 = 0; break; }
        g_is64 = is64;
    }
}

__global__ void convert_edges_kernel(const int* __restrict__ ew, int E) {
    int i = blockIdx.x * blockDim.x + threadIdx.x;
    if (i >= E) return;
    if (g_is64) {
        g_src32[i] = ew[2 * i];            // element i of row 0
        g_dst32[i] = ew[2 * E + 2 * i];    // element i of row 1 (word ofs 2E)
    } else {
        g_src32[i] = ew[i];
        g_dst32[i] = ew[E + i];
    }
}

// ------------------------------ degree / dinv ------------------------------

__global__ void init_deg_kernel(int n) {
    int i = blockIdx.x * blockDim.x + threadIdx.x;
    if (i < n) g_deg[i] = 1;  // self loop
}

__global__ void deg_hist_kernel(int E) {
    int i = blockIdx.x * blockDim.x + threadIdx.x;
    if (i < E) atomicAdd(&g_deg[g_dst32[i]], 1);
}

__global__ void dinv_kernel(int n) {
    int i = blockIdx.x * blockDim.x + threadIdx.x;
    if (i < n) g_dinv[i] = rsqrtf((float)g_deg[i]);
}

// ------------------------------ scan (CSR offsets) -------------------------

__global__ void scan_block_kernel(int n) {
    __shared__ int sm[1024];
    int t = threadIdx.x;
    int gid = blockIdx.x * 1024 + t;
    int v = (gid < n) ? (g_deg[gid] - 1) : 0;  // counts exclude self loop
    sm[t] = v;
    __syncthreads();
#pragma unroll
    for (int off = 1; off < 1024; off <<= 1) {
        int add = (t >= off) ? sm[t - off] : 0;
        __syncthreads();
        sm[t] += add;
        __syncthreads();
    }
    if (gid < n) g_rowstart[gid] = sm[t] - v;  // exclusive within block
    if (t == 1023) g_blocksums[blockIdx.x] = sm[t];
}

__global__ void scan_tops_kernel(int nb) {
    __shared__ int sm[128];
    int t = threadIdx.x;
    int v = (t < nb) ? g_blocksums[t] : 0;
    sm[t] = v;
    __syncthreads();
#pragma unroll
    for (int off = 1; off < 128; off <<= 1) {
        int add = (t >= off) ? sm[t - off] : 0;
        __syncthreads();
        sm[t] += add;
        __syncthreads();
    }
    if (t < nb) g_blocksums[t] = sm[t] - v;  // exclusive block offsets
}

__global__ void scan_fix_kernel(int n, int E) {
    int gid = blockIdx.x * blockDim.x + threadIdx.x;
    if (gid < n) {
        int v = g_rowstart[gid] + g_blocksums[gid >> 10];
        g_rowstart[gid] = v;
        g_cursor[gid]   = v;
    }
    if (gid == 0) g_rowstart[n] = E;
}

__global__ void scatter_kernel(int E) {
    int i = blockIdx.x * blockDim.x + threadIdx.x;
    if (i < E) {
        int d = g_dst32[i];
        int p = atomicAdd(&g_cursor[d], 1);
        g_colsrc[p] = g_src32[i];
    }
}

// ------------------------------ GEMM ---------------------------------------
// C[M,NOUT] = A[M,K] @ W[K,NOUT] (+bias). 64-row block tile, 256 threads,
// each thread computes 4 rows x (NOUT/16) cols.

template <int K, int NOUT, bool BIAS>
__global__ __launch_bounds__(256) void gemm_kernel(
    const float* __restrict__ Aext, int asel,
    const float* __restrict__ W, const float* __restrict__ bias,
    float* __restrict__ Cext, int csel, int M) {
    const float* A = pick_src(asel, Aext);
    float*       C = pick_dst(csel, Cext);

    constexpr int KC = 32;
    constexpr int TC = NOUT / 16;     // cols per thread
    constexpr int WP = NOUT + 4;
    __shared__ float xs[64][KC + 1];
    __shared__ float ws[KC][WP];

    int t   = threadIdx.x;
    int tr  = t >> 4;                 // rows tr*4..tr*4+3
    int tc  = t & 15;                 // cols tc*TC..+TC-1
    int row0 = blockIdx.x * 64;

    float acc[4][TC];
#pragma unroll
    for (int i = 0; i < 4; ++i)
#pragma unroll
        for (int j = 0; j < TC; ++j) acc[i][j] = 0.f;

    for (int kc = 0; kc < K; kc += KC) {
#pragma unroll
        for (int i = 0; i < (64 * KC) / 256; ++i) {
            int idx = t + i * 256;
            int r = idx >> 5, k = idx & 31;
            int gr = row0 + r;
            xs[r][k] = (gr < M) ? A[(size_t)gr * K + kc + k] : 0.f;
        }
#pragma unroll
        for (int i = 0; i < (KC * NOUT) / 256; ++i) {
            int idx = t + i * 256;
            int k = idx / NOUT, c = idx % NOUT;
            ws[k][c] = W[(kc + k) * NOUT + c];
        }
        __syncthreads();
#pragma unroll
        for (int k = 0; k < KC; ++k) {
            float xv[4], wv[TC];
#pragma unroll
            for (int i = 0; i < 4; ++i) xv[i] = xs[tr * 4 + i][k];
#pragma unroll
            for (int j = 0; j < TC; ++j) wv[j] = ws[k][tc * TC + j];
#pragma unroll
            for (int i = 0; i < 4; ++i)
#pragma unroll
                for (int j = 0; j < TC; ++j)
                    acc[i][j] = fmaf(xv[i], wv[j], acc[i][j]);
        }
        __syncthreads();
    }

#pragma unroll
    for (int i = 0; i < 4; ++i) {
        int r = row0 + tr * 4 + i;
        if (r < M) {
#pragma unroll
            for (int j = 0; j < TC; ++j) {
                int c = tc * TC + j;
                float v = acc[i][j];
                if (BIAS) v += bias[c];
                C[(size_t)r * NOUT + c] = v;
            }
        }
    }
}

// ------------------------------ aggregation --------------------------------
// One warp per destination node; 64 features as float2 per lane.
// out[d] = relu( sum_e h[src_e]*dinv[src_e]*dinv[d] + h[d]*dinv[d]^2 + b )

__global__ __launch_bounds__(256) void aggregate_kernel(
    int hsel, const float* __restrict__ bias, int osel, int n) {
    const float2* h   = (const float2*)pick_src(hsel, nullptr);
    float2*       out = (float2*)pick_dst(osel, nullptr);

    int gw   = (blockIdx.x * blockDim.x + threadIdx.x) >> 5;
    int lane = threadIdx.x & 31;
    if (gw >= n) return;
    int d = gw;
    float di = g_dinv[d];
    float2 hv = h[(size_t)d * 32 + lane];
    float sw = di * di;
    float ax = hv.x * sw, ay = hv.y * sw;

    int e0 = g_rowstart[d], e1 = g_rowstart[d + 1];
    int e  = e0;
    for (; e + 4 <= e1; e += 4) {
        int s0 = g_colsrc[e + 0];
        int s1 = g_colsrc[e + 1];
        int s2 = g_colsrc[e + 2];
        int s3 = g_colsrc[e + 3];
        float w0 = g_dinv[s0] * di;
        float w1 = g_dinv[s1] * di;
        float w2 = g_dinv[s2] * di;
        float w3 = g_dinv[s3] * di;
        float2 v0 = h[(size_t)s0 * 32 + lane];
        float2 v1 = h[(size_t)s1 * 32 + lane];
        float2 v2 = h[(size_t)s2 * 32 + lane];
        float2 v3 = h[(size_t)s3 * 32 + lane];
        ax = fmaf(v0.x, w0, ax); ay = fmaf(v0.y, w0, ay);
        ax = fmaf(v1.x, w1, ax); ay = fmaf(v1.y, w1, ay);
        ax = fmaf(v2.x, w2, ax); ay = fmaf(v2.y, w2, ay);
        ax = fmaf(v3.x, w3, ax); ay = fmaf(v3.y, w3, ay);
    }
    for (; e < e1; ++e) {
        int s = g_colsrc[e];
        float w = g_dinv[s] * di;
        float2 v = h[(size_t)s * 32 + lane];
        ax = fmaf(v.x, w, ax); ay = fmaf(v.y, w, ay);
    }

    ax += bias[2 * lane];
    ay += bias[2 * lane + 1];
    ax = fmaxf(ax, 0.f);
    ay = fmaxf(ay, 0.f);
    out[(size_t)d * 32 + lane] = make_float2(ax, ay);
}

// ------------------------------ launch -------------------------------------

extern "C" void kernel_launch(void* const* d_in, const int* in_sizes, int n_in,
                              void* d_out, int out_size) {
    const float* x   = (const float*)d_in[0];
    const int*   ew  = (const int*)d_in[1];    // edge words (int32 view)
    const float* W1  = (const float*)d_in[3];
    const float* b1  = (const float*)d_in[4];
    const float* W2  = (const float*)d_in[5];
    const float* b2  = (const float*)d_in[6];
    const float* Wfc = (const float*)d_in[7];
    const float* bfc = (const float*)d_in[8];
    float*       out = (float*)d_out;

    int n = in_sizes[0] / F_IN;
    int E = in_sizes[1] / 2;

    int nb  = (n + 1023) / 1024;       // scan blocks (<=128 for n<=131072)
    int gbN = (n + 255) / 256;
    int gbE = (E + 255) / 256;

    // ---- edge dtype detect + convert to int32 scratch
    detect_kernel<<<1, 32>>>(ew, E);
    convert_edges_kernel<<<gbE, 256>>>(ew, E);

    // ---- degrees + dinv
    init_deg_kernel<<<gbN, 256>>>(n);
    deg_hist_kernel<<<gbE, 256>>>(E);
    dinv_kernel<<<gbN, 256>>>(n);

    // ---- CSR build (by dst)
    scan_block_kernel<<<nb, 1024>>>(n);
    scan_tops_kernel<<<1, 128>>>(nb);
    scan_fix_kernel<<<gbN, 256>>>(n, E);
    scatter_kernel<<<gbE, 256>>>(E);

    int gbG1 = (n + 63) / 64;
    int gbAg = (n * 32 + 255) / 256;

    // ---- layer 1: bufA = x@W1 ; bufB = relu(agg(bufA) + b1)
    gemm_kernel<F_IN, F_HID, false><<<gbG1, 256>>>(x, 0, W1, nullptr,
                                                   nullptr, 1, n);
    aggregate_kernel<<<gbAg, 256>>>(1, b1, 2, n);
    // ---- layer 2: bufA = bufB@W2 ; bufB = relu(agg(bufA) + b2)
    gemm_kernel<F_HID, F_HID, false><<<gbG1, 256>>>(nullptr, 2, W2, nullptr,
                                                    nullptr, 1, n);
    aggregate_kernel<<<gbAg, 256>>>(1, b2, 2, n);
    // ---- FC: out = bufB@Wfc + bfc
    gemm_kernel<F_HID, F_OUT, true><<<gbG1, 256>>>(nullptr, 2, Wfc, bfc,
                                                   out, 0, n);
}

// round 5
// speedup vs baseline: 1.0997x; 1.0997x over previous
#include <cuda_runtime.h>
#include <cuda_bf16.h>
#include <cstdint>

// ---------------------------------------------------------------------------
// GCN: out = FC( relu(GCNConv2( relu(GCNConv1(x)) )) )
//   GCNConv(x): h = x@W;  out[d] = sum_{(s,d) in E} h[s]*dinv[s]*dinv[d]
//                                + h[d]*dinv[d]^2  (self loop) + b
// Edge dtype (int32 vs int64) detected on-device; hist/scatter read edges
// directly (no convert pass). Scratch = __device__ globals picked in-kernel.
// GEMM: 128x64 block tile, transposed smem A, 8x4 microtile, LDS.128 operands.
// ---------------------------------------------------------------------------

#define N_MAX 100000
#define E_MAX 1600000
#define F_IN  128
#define F_HID 64
#define F_OUT 32

__device__ int   g_is64;
__device__ int   g_deg[N_MAX];
__device__ float g_dinv[N_MAX];
__device__ int   g_rowstart[N_MAX + 1];
__device__ int   g_cursor[N_MAX];
__device__ int   g_colsrc[E_MAX];
__device__ int   g_blocksums[128];
__device__ float g_bufA[N_MAX * F_HID];
__device__ float g_bufB[N_MAX * F_HID];

__device__ __forceinline__ const float* pick_src(int sel, const float* ext) {
    if (sel == 1) return g_bufA;
    if (sel == 2) return g_bufB;
    return ext;
}
__device__ __forceinline__ float* pick_dst(int sel, float* ext) {
    if (sel == 1) return g_bufA;
    if (sel == 2) return g_bufB;
    return ext;
}

// ------------------------ edge dtype detect --------------------------------
// int64 little-endian with values < 2^31 -> every high word is 0.

__global__ void detect_kernel(const int* __restrict__ ew, int E) {
    if (threadIdx.x == 0) {
        int is64 = 1;
        for (int i = 0; i < 32; ++i)
            if (ew[2 * i + 1] != 0) { is64 = 0; break; }
        g_is64 = is64;
    }
}

// ------------------------------ degree / dinv ------------------------------

__global__ void init_deg_kernel(int n) {
    int i = blockIdx.x * blockDim.x + threadIdx.x;
    if (i < n) g_deg[i] = 1;  // self loop
}

__global__ void deg_hist_kernel(const int* __restrict__ ew, int E) {
    int i = blockIdx.x * blockDim.x + threadIdx.x;
    if (i < E) {
        int d = g_is64 ? ew[2 * E + 2 * i] : ew[E + i];
        atomicAdd(&g_deg[d], 1);
    }
}

__global__ void dinv_kernel(int n) {
    int i = blockIdx.x * blockDim.x + threadIdx.x;
    if (i < n) g_dinv[i] = rsqrtf((float)g_deg[i]);
}

// ------------------------------ scan (CSR offsets) -------------------------

__global__ void scan_block_kernel(int n) {
    __shared__ int sm[1024];
    int t = threadIdx.x;
    int gid = blockIdx.x * 1024 + t;
    int v = (gid < n) ? (g_deg[gid] - 1) : 0;  // counts exclude self loop
    sm[t] = v;
    __syncthreads();
#pragma unroll
    for (int off = 1; off < 1024; off <<= 1) {
        int add = (t >= off) ? sm[t - off] : 0;
        __syncthreads();
        sm[t] += add;
        __syncthreads();
    }
    if (gid < n) g_rowstart[gid] = sm[t] - v;  // exclusive within block
    if (t == 1023) g_blocksums[blockIdx.x] = sm[t];
}

__global__ void scan_tops_kernel(int nb) {
    __shared__ int sm[128];
    int t = threadIdx.x;
    int v = (t < nb) ? g_blocksums[t] : 0;
    sm[t] = v;
    __syncthreads();
#pragma unroll
    for (int off = 1; off < 128; off <<= 1) {
        int add = (t >= off) ? sm[t - off] : 0;
        __syncthreads();
        sm[t] += add;
        __syncthreads();
    }
    if (t < nb) g_blocksums[t] = sm[t] - v;  // exclusive block offsets
}

__global__ void scan_fix_kernel(int n, int E) {
    int gid = blockIdx.x * blockDim.x + threadIdx.x;
    if (gid < n) {
        int v = g_rowstart[gid] + g_blocksums[gid >> 10];
        g_rowstart[gid] = v;
        g_cursor[gid]   = v;
    }
    if (gid == 0) g_rowstart[n] = E;
}

__global__ void scatter_kernel(const int* __restrict__ ew, int E) {
    int i = blockIdx.x * blockDim.x + threadIdx.x;
    if (i < E) {
        int d, s;
        if (g_is64) {
            s = ew[2 * i];
            d = ew[2 * E + 2 * i];
        } else {
            s = ew[i];
            d = ew[E + i];
        }
        int p = atomicAdd(&g_cursor[d], 1);
        g_colsrc[p] = s;
    }
}

// ------------------------------ GEMM ---------------------------------------
// C[M,NOUT] = A[M,K] @ W[K,NOUT] (+bias). 128-row tile, 256 threads,
// 8x(NOUT/16) microtile, transposed smem A, LDS.128 operand reads.

template <int K, int NOUT, bool BIAS>
__global__ __launch_bounds__(256) void gemm_kernel(
    const float* __restrict__ Aext, int asel,
    const float* __restrict__ W, const float* __restrict__ bias,
    float* __restrict__ Cext, int csel, int M) {
    const float* A = pick_src(asel, Aext);
    float*       C = pick_dst(csel, Cext);

    constexpr int KC  = 32;
    constexpr int MT  = 128;
    constexpr int TC  = NOUT / 16;          // 4 (NOUT=64) or 2 (NOUT=32)
    constexpr int MS  = MT + 4;             // xsT row stride (16B aligned)
    constexpr int WS  = NOUT + 4;           // ws row stride (16B aligned)
    __shared__ float xsT[KC][MS];           // transposed: [k][m]
    __shared__ float ws[KC][WS];

    int t    = threadIdx.x;
    int rg   = t >> 4;                      // rowgroup: rows rg*8..+8
    int cg   = t & 15;                      // colgroup: cols cg*TC..+TC
    int row0 = blockIdx.x * MT;

    float acc[8][TC];
#pragma unroll
    for (int i = 0; i < 8; ++i)
#pragma unroll
        for (int j = 0; j < TC; ++j) acc[i][j] = 0.f;

    for (int kc = 0; kc < K; kc += KC) {
        // stage A tile (transposed): 128 rows x 32 k. 1024 float4 / 256 thr.
#pragma unroll
        for (int i = 0; i < 4; ++i) {
            int f4 = t + i * 256;
            int r  = f4 >> 3;               // 0..127
            int k4 = (f4 & 7) * 4;          // 0,4,...,28
            float4 v = make_float4(0.f, 0.f, 0.f, 0.f);
            int gr = row0 + r;
            if (gr < M)
                v = *(const float4*)&A[(size_t)gr * K + kc + k4];
            xsT[k4 + 0][r] = v.x;
            xsT[k4 + 1][r] = v.y;
            xsT[k4 + 2][r] = v.z;
            xsT[k4 + 3][r] = v.w;
        }
        // stage W tile: 32 x NOUT. KC*NOUT/4 float4 / 256 thr.
#pragma unroll
        for (int i = 0; i < (KC * NOUT) / 1024; ++i) {
            int f4 = t + i * 256;
            int k  = f4 / (NOUT / 4);
            int c4 = (f4 % (NOUT / 4)) * 4;
            *(float4*)&ws[k][c4] = *(const float4*)&W[(kc + k) * NOUT + c4];
        }
        __syncthreads();
#pragma unroll
        for (int k = 0; k < KC; ++k) {
            float4 x0 = *(const float4*)&xsT[k][rg * 8];
            float4 x1 = *(const float4*)&xsT[k][rg * 8 + 4];
            float xv[8] = {x0.x, x0.y, x0.z, x0.w, x1.x, x1.y, x1.z, x1.w};
            float wv[TC];
            if (TC == 4) {
                float4 w4 = *(const float4*)&ws[k][cg * 4];
                wv[0] = w4.x; wv[1] = w4.y; wv[2] = w4.z; wv[3] = w4.w;
            } else {
                float2 w2 = *(const float2*)&ws[k][cg * 2];
                wv[0] = w2.x; wv[1] = w2.y;
            }
#pragma unroll
            for (int i = 0; i < 8; ++i)
#pragma unroll
                for (int j = 0; j < TC; ++j)
                    acc[i][j] = fmaf(xv[i], wv[j], acc[i][j]);
        }
        __syncthreads();
    }

#pragma unroll
    for (int i = 0; i < 8; ++i) {
        int r = row0 + rg * 8 + i;
        if (r < M) {
#pragma unroll
            for (int j = 0; j < TC; ++j) {
                int c = cg * TC + j;
                float v = acc[i][j];
                if (BIAS) v += bias[c];
                C[(size_t)r * NOUT + c] = v;
            }
        }
    }
}

// ------------------------------ aggregation --------------------------------
// One warp per destination node; 64 features as float2 per lane.
// out[d] = relu( sum_e h[src_e]*dinv[src_e]*dinv[d] + h[d]*dinv[d]^2 + b )

__global__ __launch_bounds__(256) void aggregate_kernel(
    int hsel, const float* __restrict__ bias, int osel, int n) {
    const float2* h   = (const float2*)pick_src(hsel, nullptr);
    float2*       out = (float2*)pick_dst(osel, nullptr);

    int gw   = (blockIdx.x * blockDim.x + threadIdx.x) >> 5;
    int lane = threadIdx.x & 31;
    if (gw >= n) return;
    int d = gw;
    float di = g_dinv[d];
    float2 hv = h[(size_t)d * 32 + lane];
    float sw = di * di;
    float ax = hv.x * sw, ay = hv.y * sw;

    int e0 = g_rowstart[d], e1 = g_rowstart[d + 1];
    int e  = e0;
    for (; e + 4 <= e1; e += 4) {
        int s0 = g_colsrc[e + 0];
        int s1 = g_colsrc[e + 1];
        int s2 = g_colsrc[e + 2];
        int s3 = g_colsrc[e + 3];
        float w0 = g_dinv[s0] * di;
        float w1 = g_dinv[s1] * di;
        float w2 = g_dinv[s2] * di;
        float w3 = g_dinv[s3] * di;
        float2 v0 = h[(size_t)s0 * 32 + lane];
        float2 v1 = h[(size_t)s1 * 32 + lane];
        float2 v2 = h[(size_t)s2 * 32 + lane];
        float2 v3 = h[(size_t)s3 * 32 + lane];
        ax = fmaf(v0.x, w0, ax); ay = fmaf(v0.y, w0, ay);
        ax = fmaf(v1.x, w1, ax); ay = fmaf(v1.y, w1, ay);
        ax = fmaf(v2.x, w2, ax); ay = fmaf(v2.y, w2, ay);
        ax = fmaf(v3.x, w3, ax); ay = fmaf(v3.y, w3, ay);
    }
    for (; e < e1; ++e) {
        int s = g_colsrc[e];
        float w = g_dinv[s] * di;
        float2 v = h[(size_t)s * 32 + lane];
        ax = fmaf(v.x, w, ax); ay = fmaf(v.y, w, ay);
    }

    ax += bias[2 * lane];
    ay += bias[2 * lane + 1];
    ax = fmaxf(ax, 0.f);
    ay = fmaxf(ay, 0.f);
    out[(size_t)d * 32 + lane] = make_float2(ax, ay);
}

// ------------------------------ launch -------------------------------------

extern "C" void kernel_launch(void* const* d_in, const int* in_sizes, int n_in,
                              void* d_out, int out_size) {
    const float* x   = (const float*)d_in[0];
    const int*   ew  = (const int*)d_in[1];    // edge words (int32 view)
    const float* W1  = (const float*)d_in[3];
    const float* b1  = (const float*)d_in[4];
    const float* W2  = (const float*)d_in[5];
    const float* b2  = (const float*)d_in[6];
    const float* Wfc = (const float*)d_in[7];
    const float* bfc = (const float*)d_in[8];
    float*       out = (float*)d_out;

    int n = in_sizes[0] / F_IN;
    int E = in_sizes[1] / 2;

    int nb  = (n + 1023) / 1024;       // scan blocks (<=128 for n<=131072)
    int gbN = (n + 255) / 256;
    int gbE = (E + 255) / 256;

    // ---- edge dtype detect
    detect_kernel<<<1, 32>>>(ew, E);

    // ---- degrees + dinv
    init_deg_kernel<<<gbN, 256>>>(n);
    deg_hist_kernel<<<gbE, 256>>>(ew, E);
    dinv_kernel<<<gbN, 256>>>(n);

    // ---- CSR build (by dst)
    scan_block_kernel<<<nb, 1024>>>(n);
    scan_tops_kernel<<<1, 128>>>(nb);
    scan_fix_kernel<<<gbN, 256>>>(n, E);
    scatter_kernel<<<gbE, 256>>>(ew, E);

    int gbG  = (n + 127) / 128;
    int gbAg = (n * 32 + 255) / 256;

    // ---- layer 1: bufA = x@W1 ; bufB = relu(agg(bufA) + b1)
    gemm_kernel<F_IN, F_HID, false><<<gbG, 256>>>(x, 0, W1, nullptr,
                                                  nullptr, 1, n);
    aggregate_kernel<<<gbAg, 256>>>(1, b1, 2, n);
    // ---- layer 2: bufA = bufB@W2 ; bufB = relu(agg(bufA) + b2)
    gemm_kernel<F_HID, F_HID, false><<<gbG, 256>>>(nullptr, 2, W2, nullptr,
                                                   nullptr, 1, n);
    aggregate_kernel<<<gbAg, 256>>>(1, b2, 2, n);
    // ---- FC: out = bufB@Wfc + bfc
    gemm_kernel<F_HID, F_OUT, true><<<gbG, 256>>>(nullptr, 2, Wfc, bfc,
                                                  out, 0, n);
}

// round 8
// speedup vs baseline: 1.4749x; 1.3412x over previous
#include <cuda_runtime.h>
#include <cuda_bf16.h>
#include <cstdint>

// ---------------------------------------------------------------------------
// GCN via TF32 tensor-core GEMMs + CSR warp aggregation.
//   hs = (x@W) * dinv[row]   (dinv folded into GEMM epilogue)
//   out[d] = relu( (hs[d] + sum_{e->d} hs[src]) * dinv[d] + b )
// ---------------------------------------------------------------------------

#define N_MAX 100000
#define E_MAX 1600000
#define F_IN  128
#define F_HID 64
#define F_OUT 32

__device__ int   g_is64;
__device__ int   g_deg[N_MAX];
__device__ float g_dinv[N_MAX];
__device__ int   g_rowstart[N_MAX + 1];
__device__ int   g_cursor[N_MAX];
__device__ int   g_colsrc[E_MAX];
__device__ int   g_blocksums[128];
__device__ float g_bufA[N_MAX * F_HID];
__device__ float g_bufB[N_MAX * F_HID];

__device__ __forceinline__ const float* pick_src(int sel, const float* ext) {
    if (sel == 1) return g_bufA;
    if (sel == 2) return g_bufB;
    return ext;
}
__device__ __forceinline__ float* pick_dst(int sel, float* ext) {
    if (sel == 1) return g_bufA;
    if (sel == 2) return g_bufB;
    return ext;
}

__device__ __forceinline__ uint32_t f2tf32(float f) {
    uint32_t u;
    asm("cvt.rna.tf32.f32 %0, %1;" : "=r"(u) : "f"(f));
    return u;
}

__device__ __forceinline__ void mma_tf32(float* c, const uint32_t* a,
                                         uint32_t b0, uint32_t b1) {
    asm volatile(
        "mma.sync.aligned.m16n8k8.row.col.f32.tf32.tf32.f32 "
        "{%0,%1,%2,%3}, {%4,%5,%6,%7}, {%8,%9}, {%0,%1,%2,%3};"
        : "+f"(c[0]), "+f"(c[1]), "+f"(c[2]), "+f"(c[3])
        : "r"(a[0]), "r"(a[1]), "r"(a[2]), "r"(a[3]), "r"(b0), "r"(b1));
}

// ------------------------ edge dtype detect --------------------------------

__global__ void detect_kernel(const int* __restrict__ ew, int E) {
    if (threadIdx.x == 0) {
        int is64 = 1;
        for (int i = 0; i < 32; ++i)
            if (ew[2 * i + 1] != 0) { is64 = 0; break; }
        g_is64 = is64;
    }
}

// ------------------------------ degree -------------------------------------

__global__ void init_deg_kernel(int n) {
    int i = blockIdx.x * blockDim.x + threadIdx.x;
    if (i < n) g_deg[i] = 1;  // self loop
}

__global__ void deg_hist_kernel(const int* __restrict__ ew, int E) {
    int i = blockIdx.x * blockDim.x + threadIdx.x;
    if (i < E) {
        int d = g_is64 ? ew[2 * E + 2 * i] : ew[E + i];
        atomicAdd(&g_deg[d], 1);
    }
}

// ------------------------------ scan (CSR offsets) -------------------------

__global__ void scan_block_kernel(int n) {
    __shared__ int wsum[32];
    int t = threadIdx.x, lane = t & 31, wid = t >> 5;
    int gid = blockIdx.x * 1024 + t;
    int v = (gid < n) ? (g_deg[gid] - 1) : 0;  // counts exclude self loop
    int s = v;
#pragma unroll
    for (int off = 1; off < 32; off <<= 1) {
        int u = __shfl_up_sync(0xffffffffu, s, off);
        if (lane >= off) s += u;
    }
    if (lane == 31) wsum[wid] = s;
    __syncthreads();
    if (wid == 0) {
        int wv = wsum[lane];
        int ss = wv;
#pragma unroll
        for (int off = 1; off < 32; off <<= 1) {
            int u = __shfl_up_sync(0xffffffffu, ss, off);
            if (lane >= off) ss += u;
        }
        wsum[lane] = ss - wv;                  // exclusive warp offsets
        if (lane == 31) g_blocksums[blockIdx.x] = ss;  // block total
    }
    __syncthreads();
    if (gid < n) g_rowstart[gid] = s - v + wsum[wid];  // exclusive in block
}

__global__ void scan_tops_kernel(int nb) {
    __shared__ int sm[128];
    int t = threadIdx.x;
    int v = (t < nb) ? g_blocksums[t] : 0;
    sm[t] = v;
    __syncthreads();
#pragma unroll
    for (int off = 1; off < 128; off <<= 1) {
        int add = (t >= off) ? sm[t - off] : 0;
        __syncthreads();
        sm[t] += add;
        __syncthreads();
    }
    if (t < nb) g_blocksums[t] = sm[t] - v;  // exclusive block offsets
}

// also computes dinv (fused to save a launch)
__global__ void scan_fix_kernel(int n, int E) {
    int gid = blockIdx.x * blockDim.x + threadIdx.x;
    if (gid < n) {
        int v = g_rowstart[gid] + g_blocksums[gid >> 10];
        g_rowstart[gid] = v;
        g_cursor[gid]   = v;
        g_dinv[gid]     = rsqrtf((float)g_deg[gid]);
    }
    if (gid == 0) g_rowstart[n] = E;
}

__global__ void scatter_kernel(const int* __restrict__ ew, int E) {
    int i = blockIdx.x * blockDim.x + threadIdx.x;
    if (i < E) {
        int d, s;
        if (g_is64) {
            s = ew[2 * i];
            d = ew[2 * E + 2 * i];
        } else {
            s = ew[i];
            d = ew[E + i];
        }
        int p = atomicAdd(&g_cursor[d], 1);
        g_colsrc[p] = s;
    }
}

// ------------------------------ TF32 MMA GEMM ------------------------------
// C[M,NOUT] = A[M,K] @ W[K,NOUT]; optional row-scale by dinv (DINV) or +bias.
// 256 thr = 8 warps in 4x2; warp tile 32 x (NOUT/2); m16n8k8 fragments.
// smem strides chosen so all fragment LDS are bank-conflict-free.

template <int K, int NOUT, bool DINV, bool BIAS>
__global__ __launch_bounds__(256) void mma_gemm_kernel(
    const float* __restrict__ Aext, int asel,
    const float* __restrict__ W, const float* __restrict__ bias,
    float* __restrict__ Cext, int csel, int M) {
    const float* A = pick_src(asel, Aext);
    float*       C = pick_dst(csel, Cext);

    constexpr int KC = 32;
    constexpr int AS = KC + 4;           // bank = (4g+tig)%32 : distinct
    constexpr int WS = NOUT + 8;         // bank = (8tig+g)%32 : distinct
    constexpr int WARP_N = NOUT / 2;     // 32 or 16
    constexpr int NF = WARP_N / 8;       // 4 or 2
    __shared__ float xs[128][AS];        // tf32 bits
    __shared__ float ws[KC][WS];         // tf32 bits

    int t    = threadIdx.x;
    int wid  = t >> 5, lane = t & 31;
    int wm   = wid >> 1;                 // 0..3 -> rows wm*32
    int wn   = wid & 1;                  // cols wn*WARP_N
    int g    = lane >> 2, tig = lane & 3;
    int row0 = blockIdx.x * 128;

    float c[2][NF][4];
#pragma unroll
    for (int mf = 0; mf < 2; ++mf)
#pragma unroll
        for (int nf = 0; nf < NF; ++nf)
#pragma unroll
            for (int j = 0; j < 4; ++j) c[mf][nf][j] = 0.f;

    for (int kc = 0; kc < K; kc += KC) {
        // stage A (tf32): 128 x 32, 4 float4 per thread, conflict-free STS.128
#pragma unroll
        for (int i = 0; i < 4; ++i) {
            int f4 = t + i * 256;
            int r  = f4 >> 3;
            int k4 = (f4 & 7) * 4;
            float4 v = make_float4(0.f, 0.f, 0.f, 0.f);
            int gr = row0 + r;
            if (gr < M) v = *(const float4*)&A[(size_t)gr * K + kc + k4];
            float4 tv;
            tv.x = __uint_as_float(f2tf32(v.x));
            tv.y = __uint_as_float(f2tf32(v.y));
            tv.z = __uint_as_float(f2tf32(v.z));
            tv.w = __uint_as_float(f2tf32(v.w));
            *(float4*)&xs[r][k4] = tv;
        }
        // stage W (tf32): 32 x NOUT
#pragma unroll
        for (int i = 0; i < (KC * NOUT) / 1024; ++i) {
            int f4 = t + i * 256;
            int k  = f4 / (NOUT / 4);
            int c4 = (f4 % (NOUT / 4)) * 4;
            float4 v = *(const float4*)&W[(kc + k) * NOUT + c4];
            float4 tv;
            tv.x = __uint_as_float(f2tf32(v.x));
            tv.y = __uint_as_float(f2tf32(v.y));
            tv.z = __uint_as_float(f2tf32(v.z));
            tv.w = __uint_as_float(f2tf32(v.w));
            *(float4*)&ws[k][c4] = tv;
        }
        __syncthreads();
#pragma unroll
        for (int ks = 0; ks < KC / 8; ++ks) {
            int k0 = ks * 8;
            uint32_t a[2][4];
#pragma unroll
            for (int mf = 0; mf < 2; ++mf) {
                int rb = wm * 32 + mf * 16 + g;
                a[mf][0] = __float_as_uint(xs[rb][k0 + tig]);
                a[mf][1] = __float_as_uint(xs[rb + 8][k0 + tig]);
                a[mf][2] = __float_as_uint(xs[rb][k0 + tig + 4]);
                a[mf][3] = __float_as_uint(xs[rb + 8][k0 + tig + 4]);
            }
#pragma unroll
            for (int nf = 0; nf < NF; ++nf) {
                int nb = wn * WARP_N + nf * 8 + g;
                uint32_t b0 = __float_as_uint(ws[k0 + tig][nb]);
                uint32_t b1 = __float_as_uint(ws[k0 + tig + 4][nb]);
                mma_tf32(c[0][nf], a[0], b0, b1);
                mma_tf32(c[1][nf], a[1], b0, b1);
            }
        }
        __syncthreads();
    }

    // epilogue
#pragma unroll
    for (int mf = 0; mf < 2; ++mf) {
        int rA = row0 + wm * 32 + mf * 16 + g;
        int rB = rA + 8;
        float sA = 1.f, sB = 1.f;
        if (DINV) {
            if (rA < M) sA = g_dinv[rA];
            if (rB < M) sB = g_dinv[rB];
        }
#pragma unroll
        for (int nf = 0; nf < NF; ++nf) {
            int cb = wn * WARP_N + nf * 8 + tig * 2;
            float b0 = 0.f, b1 = 0.f;
            if (BIAS) { b0 = bias[cb]; b1 = bias[cb + 1]; }
            if (rA < M) {
                float2 v = make_float2(c[mf][nf][0] * sA + b0,
                                       c[mf][nf][1] * sA + b1);
                *(float2*)&C[(size_t)rA * NOUT + cb] = v;
            }
            if (rB < M) {
                float2 v = make_float2(c[mf][nf][2] * sB + b0,
                                       c[mf][nf][3] * sB + b1);
                *(float2*)&C[(size_t)rB * NOUT + cb] = v;
            }
        }
    }
}

// ------------------------------ aggregation --------------------------------
// hs already row-scaled by dinv[src]. One warp per dst node.
// out[d] = relu( (hs[d] + sum_e hs[src_e]) * dinv[d] + b )

__global__ __launch_bounds__(256) void aggregate_kernel(
    int hsel, const float* __restrict__ bias, int osel, int n) {
    const float2* h   = (const float2*)pick_src(hsel, nullptr);
    float2*       out = (float2*)pick_dst(osel, nullptr);

    int gw   = (blockIdx.x * blockDim.x + threadIdx.x) >> 5;
    int lane = threadIdx.x & 31;
    if (gw >= n) return;
    int d = gw;
    float di = g_dinv[d];
    float2 hv = h[(size_t)d * 32 + lane];
    float ax = hv.x, ay = hv.y;          // self term (hs[d])

    int e0 = g_rowstart[d], e1 = g_rowstart[d + 1];
    int e  = e0;
    for (; e + 4 <= e1; e += 4) {
        int s0 = g_colsrc[e + 0];
        int s1 = g_colsrc[e + 1];
        int s2 = g_colsrc[e + 2];
        int s3 = g_colsrc[e + 3];
        float2 v0 = h[(size_t)s0 * 32 + lane];
        float2 v1 = h[(size_t)s1 * 32 + lane];
        float2 v2 = h[(size_t)s2 * 32 + lane];
        float2 v3 = h[(size_t)s3 * 32 + lane];
        ax += v0.x; ay += v0.y;
        ax += v1.x; ay += v1.y;
        ax += v2.x; ay += v2.y;
        ax += v3.x; ay += v3.y;
    }
    for (; e < e1; ++e) {
        int s = g_colsrc[e];
        float2 v = h[(size_t)s * 32 + lane];
        ax += v.x; ay += v.y;
    }

    ax = fmaf(ax, di, bias[2 * lane]);
    ay = fmaf(ay, di, bias[2 * lane + 1]);
    ax = fmaxf(ax, 0.f);
    ay = fmaxf(ay, 0.f);
    out[(size_t)d * 32 + lane] = make_float2(ax, ay);
}

// ------------------------------ launch -------------------------------------

extern "C" void kernel_launch(void* const* d_in, const int* in_sizes, int n_in,
                              void* d_out, int out_size) {
    const float* x   = (const float*)d_in[0];
    const int*   ew  = (const int*)d_in[1];    // edge words (int32 view)
    const float* W1  = (const float*)d_in[3];
    const float* b1  = (const float*)d_in[4];
    const float* W2  = (const float*)d_in[5];
    const float* b2  = (const float*)d_in[6];
    const float* Wfc = (const float*)d_in[7];
    const float* bfc = (const float*)d_in[8];
    float*       out = (float*)d_out;

    int n = in_sizes[0] / F_IN;
    int E = in_sizes[1] / 2;

    int nb  = (n + 1023) / 1024;
    int gbN = (n + 255) / 256;
    int gbE = (E + 255) / 256;

    detect_kernel<<<1, 32>>>(ew, E);
    init_deg_kernel<<<gbN, 256>>>(n);
    deg_hist_kernel<<<gbE, 256>>>(ew, E);
    scan_block_kernel<<<nb, 1024>>>(n);
    scan_tops_kernel<<<1, 128>>>(nb);
    scan_fix_kernel<<<gbN, 256>>>(n, E);   // + dinv
    scatter_kernel<<<gbE, 256>>>(ew, E);

    int gbG  = (n + 127) / 128;
    int gbAg = (n * 32 + 255) / 256;

    // layer 1: bufA = (x@W1)*dinv ; bufB = relu(agg*dinv + b1)
    mma_gemm_kernel<F_IN, F_HID, true, false><<<gbG, 256>>>(
        x, 0, W1, nullptr, nullptr, 1, n);
    aggregate_kernel<<<gbAg, 256>>>(1, b1, 2, n);
    // layer 2
    mma_gemm_kernel<F_HID, F_HID, true, false><<<gbG, 256>>>(
        nullptr, 2, W2, nullptr, nullptr, 1, n);
    aggregate_kernel<<<gbAg, 256>>>(1, b2, 2, n);
    // FC: out = bufB@Wfc + bfc
    mma_gemm_kernel<F_HID, F_OUT, false, true><<<gbG, 256>>>(
        nullptr, 2, Wfc, bfc, out, 0, n);
}